// round 9
// baseline (speedup 1.0000x reference)
#include <cuda_runtime.h>
#include <cstdint>

// Problem shape (fixed by the dataset).
#define BDIM   8
#define NROWS  2048
#define LCOLS  2048
#define QROWS  512
#define DDIM   512
#define NHEAD  4

// Scratch: per (b, l, head) one float4 = {w0, w1, w2, bitcast(i0|i1<<10|i2<<20)}.
__device__ float4 g_tw[(size_t)BDIM * LCOLS * NHEAD];

// ---------------------------------------------------------------------------
// Kernel 1: top-3 + softmax, q-split 4 ways for occupancy + shorter dep chain.
// Block = (128 l, 4 segments). Each thread scans 128 rows (coalesced across l),
// partial top-3s merged in smem preserving top_k's first-index-wins tie rule.
// ---------------------------------------------------------------------------
__global__ __launch_bounds__(512) void topk_softmax_kernel(
    const float* __restrict__ logits)
{
    const int x = threadIdx.x;            // l within tile
    const int s = threadIdx.y;            // q segment 0..3
    const int l = blockIdx.x * 128 + x;
    const int h = blockIdx.y;
    const int b = blockIdx.z;

    const float* p = logits
        + ((size_t)b * NROWS + (size_t)h * QROWS + (size_t)s * 128) * LCOLS + l;

    float t0 = -3.4e38f, t1 = -3.4e38f, t2 = -3.4e38f;
    int   i0 = 0, i1 = 0, i2 = 0;

#pragma unroll 8
    for (int j = 0; j < 128; ++j) {
        float v = __ldg(p + (size_t)j * LCOLS);
        if (v > t0)      { t2 = t1; i2 = i1; t1 = t0; i1 = i0; t0 = v; i0 = j; }
        else if (v > t1) { t2 = t1; i2 = i1; t1 = v;  i1 = j; }
        else if (v > t2) { t2 = v;  i2 = j; }
    }

    __shared__ float4 sm[4][128];
    {
        // global indices fit in 9 bits each
        unsigned pk = (unsigned)(i0 + s * 128)
                    | ((unsigned)(i1 + s * 128) << 9)
                    | ((unsigned)(i2 + s * 128) << 18);
        sm[s][x] = make_float4(t0, t1, t2, __uint_as_float(pk));
    }
    __syncthreads();

    if (s == 0) {
        float m0 = -3.4e38f, m1 = -3.4e38f, m2 = -3.4e38f;
        int   j0 = 0, j1 = 0, j2 = 0;
        // Candidates processed in ascending global index among equals:
        // segment ascending, and within a segment k ascending (index-ordered
        // among equal values). Strict '>' keeps earlier candidates ahead.
#pragma unroll
        for (int ss = 0; ss < 4; ++ss) {
            float4 c = sm[ss][x];
            unsigned pk = __float_as_uint(c.w);
            float cv[3] = { c.x, c.y, c.z };
            int   ci[3] = { (int)( pk        & 511),
                            (int)((pk >> 9)  & 511),
                            (int)((pk >> 18) & 511) };
#pragma unroll
            for (int k = 0; k < 3; ++k) {
                float v = cv[k]; int idx = ci[k];
                if (v > m0)      { m2 = m1; j2 = j1; m1 = m0; j1 = j0; m0 = v; j0 = idx; }
                else if (v > m1) { m2 = m1; j2 = j1; m1 = v;  j1 = idx; }
                else if (v > m2) { m2 = v;  j2 = idx; }
            }
        }

        float e1  = __expf(m1 - m0);
        float e2  = __expf(m2 - m0);
        float inv = 1.0f / (1.0f + e1 + e2);

        float4 r;
        r.x = inv;
        r.y = e1 * inv;
        r.z = e2 * inv;
        r.w = __uint_as_float((unsigned)j0 | ((unsigned)j1 << 10)
                              | ((unsigned)j2 << 20));
        g_tw[((size_t)b * LCOLS + l) * NHEAD + h] = r;
    }
}

// ---------------------------------------------------------------------------
// Kernel 2: combine. Warp-per-l (lanes cover d) => every embedding-row gather
// is a fully coalesced 512B request (4 sectors/LDG vs 32 before).
// Padded smem tile transposes (l-major accum) -> (d-major, l-contiguous) for
// coalesced global stores.
// ---------------------------------------------------------------------------
#define K2_WARPS 8
#define K2_WL    2                       // l's per warp
#define K2_LT    (K2_WARPS * K2_WL)      // 16 l per block
#define K2_PAD   516                     // smem row stride (floats), 16B-aligned

__global__ __launch_bounds__(256) void combine_kernel(
    const float* __restrict__ e0, const float* __restrict__ e1,
    const float* __restrict__ e2, const float* __restrict__ e3,
    float* __restrict__ out)
{
    const int tid   = threadIdx.x;
    const int warp  = tid >> 5;
    const int lane  = tid & 31;
    const int lbase = blockIdx.x * K2_LT;
    const int b     = blockIdx.y;

    const float* embs[NHEAD] = { e0, e1, e2, e3 };

    __shared__ float sm[K2_LT][K2_PAD];

    float4 acc[K2_WL][4];
#pragma unroll
    for (int il = 0; il < K2_WL; ++il)
#pragma unroll
        for (int c = 0; c < 4; ++c)
            acc[il][c] = make_float4(0.f, 0.f, 0.f, 0.f);

#pragma unroll
    for (int il = 0; il < K2_WL; ++il) {
        const int l = lbase + warp * K2_WL + il;
#pragma unroll
        for (int h = 0; h < NHEAD; ++h) {
            float4 tw = g_tw[((size_t)b * LCOLS + l) * NHEAD + h];
            unsigned pk = __float_as_uint(tw.w);
            float w[3]   = { tw.x, tw.y, tw.z };
            int   idx[3] = { (int)( pk        & 0x3FF),
                             (int)((pk >> 10) & 0x3FF),
                             (int)((pk >> 20) & 0x3FF) };
#pragma unroll
            for (int k = 0; k < 3; ++k) {
                const float4* row =
                    (const float4*)(embs[h] + (size_t)idx[k] * DDIM) + lane;
                const float wk = w[k];
#pragma unroll
                for (int c = 0; c < 4; ++c) {
                    float4 v = __ldg(row + c * 32);
                    acc[il][c].x = fmaf(wk, v.x, acc[il][c].x);
                    acc[il][c].y = fmaf(wk, v.y, acc[il][c].y);
                    acc[il][c].z = fmaf(wk, v.z, acc[il][c].z);
                    acc[il][c].w = fmaf(wk, v.w, acc[il][c].w);
                }
            }
        }
    }

    // accum (lanes over d) -> smem[l][d]
#pragma unroll
    for (int il = 0; il < K2_WL; ++il) {
        const int lrow = warp * K2_WL + il;
#pragma unroll
        for (int c = 0; c < 4; ++c)
            *(float4*)&sm[lrow][c * 128 + lane * 4] = acc[il][c];
    }
    __syncthreads();

    // coalesced stores: consecutive threads -> consecutive l
    float* obase = out + (size_t)b * DDIM * LCOLS + lbase;
#pragma unroll
    for (int r = 0; r < (DDIM * K2_LT) / 256; ++r) {
        int linear = r * 256 + tid;
        int d = linear >> 4;          // /16
        int l = linear & 15;
        obase[(size_t)d * LCOLS + l] = sm[l][d];
    }
}

// ---------------------------------------------------------------------------
extern "C" void kernel_launch(void* const* d_in, const int* in_sizes, int n_in,
                              void* d_out, int out_size)
{
    const float* logits = (const float*)d_in[0];
    const float* e0     = (const float*)d_in[1];
    const float* e1     = (const float*)d_in[2];
    const float* e2     = (const float*)d_in[3];
    const float* e3     = (const float*)d_in[4];
    float*       out    = (float*)d_out;

    dim3 g1(LCOLS / 128, NHEAD, BDIM);     // (16, 4, 8) = 512 blocks of 512 thr
    dim3 b1(128, 4, 1);
    topk_softmax_kernel<<<g1, b1>>>(logits);

    dim3 g2(LCOLS / K2_LT, BDIM, 1);       // (128, 8) = 1024 blocks of 256 thr
    combine_kernel<<<g2, 256>>>(e0, e1, e2, e3, out);
}

// round 11
// speedup vs baseline: 1.0264x; 1.0264x over previous
#include <cuda_runtime.h>
#include <cstdint>

// Problem shape (fixed by the dataset).
#define BDIM   8
#define NROWS  2048
#define LCOLS  2048
#define QROWS  512
#define DDIM   512
#define NHEAD  4

// Scratch: per (b, l, head) one float4 = {w0, w1, w2, bitcast(i0|i1<<10|i2<<20)}.
__device__ float4 g_tw[(size_t)BDIM * LCOLS * NHEAD];

// ---------------------------------------------------------------------------
// Kernel 1: top-3 + softmax, q-split 4 ways for occupancy + shorter dep chain.
// Block = (128 l, 4 segments). Each thread scans 128 rows (coalesced across l),
// partial top-3s merged in smem preserving top_k's first-index-wins tie rule.
// ---------------------------------------------------------------------------
__global__ __launch_bounds__(512) void topk_softmax_kernel(
    const float* __restrict__ logits)
{
    const int x = threadIdx.x;            // l within tile
    const int s = threadIdx.y;            // q segment 0..3
    const int l = blockIdx.x * 128 + x;
    const int h = blockIdx.y;
    const int b = blockIdx.z;

    const float* p = logits
        + ((size_t)b * NROWS + (size_t)h * QROWS + (size_t)s * 128) * LCOLS + l;

    float t0 = -3.4e38f, t1 = -3.4e38f, t2 = -3.4e38f;
    int   i0 = 0, i1 = 0, i2 = 0;

#pragma unroll 8
    for (int j = 0; j < 128; ++j) {
        float v = __ldg(p + (size_t)j * LCOLS);
        if (v > t0)      { t2 = t1; i2 = i1; t1 = t0; i1 = i0; t0 = v; i0 = j; }
        else if (v > t1) { t2 = t1; i2 = i1; t1 = v;  i1 = j; }
        else if (v > t2) { t2 = v;  i2 = j; }
    }

    __shared__ float4 sm[4][128];
    {
        // global indices fit in 9 bits each
        unsigned pk = (unsigned)(i0 + s * 128)
                    | ((unsigned)(i1 + s * 128) << 9)
                    | ((unsigned)(i2 + s * 128) << 18);
        sm[s][x] = make_float4(t0, t1, t2, __uint_as_float(pk));
    }
    __syncthreads();

    if (s == 0) {
        float m0 = -3.4e38f, m1 = -3.4e38f, m2 = -3.4e38f;
        int   j0 = 0, j1 = 0, j2 = 0;
        // Candidates processed in ascending global index among equals:
        // segment ascending, and within a segment k ascending (index-ordered
        // among equal values). Strict '>' keeps earlier candidates ahead.
#pragma unroll
        for (int ss = 0; ss < 4; ++ss) {
            float4 c = sm[ss][x];
            unsigned pk = __float_as_uint(c.w);
            float cv[3] = { c.x, c.y, c.z };
            int   ci[3] = { (int)( pk        & 511),
                            (int)((pk >> 9)  & 511),
                            (int)((pk >> 18) & 511) };
#pragma unroll
            for (int k = 0; k < 3; ++k) {
                float v = cv[k]; int idx = ci[k];
                if (v > m0)      { m2 = m1; j2 = j1; m1 = m0; j1 = j0; m0 = v; j0 = idx; }
                else if (v > m1) { m2 = m1; j2 = j1; m1 = v;  j1 = idx; }
                else if (v > m2) { m2 = v;  j2 = idx; }
            }
        }

        float e1  = __expf(m1 - m0);
        float e2  = __expf(m2 - m0);
        float inv = 1.0f / (1.0f + e1 + e2);

        float4 r;
        r.x = inv;
        r.y = e1 * inv;
        r.z = e2 * inv;
        r.w = __uint_as_float((unsigned)j0 | ((unsigned)j1 << 10)
                              | ((unsigned)j2 << 20));
        g_tw[((size_t)b * LCOLS + l) * NHEAD + h] = r;
    }
}

// ---------------------------------------------------------------------------
// Kernel 2: combine. Warp-per-l (lanes cover d) => every embedding-row gather
// is a fully coalesced 512B request (4 sectors/LDG vs 32 before).
// Padded smem tile transposes (l-major accum) -> (d-major, l-contiguous) for
// coalesced global stores.
// ---------------------------------------------------------------------------
#define K2_WARPS 8
#define K2_WL    2                       // l's per warp
#define K2_LT    (K2_WARPS * K2_WL)      // 16 l per block
#define K2_PAD   516                     // smem row stride (floats), 16B-aligned

__global__ __launch_bounds__(256) void combine_kernel(
    const float* __restrict__ e0, const float* __restrict__ e1,
    const float* __restrict__ e2, const float* __restrict__ e3,
    float* __restrict__ out)
{
    const int tid   = threadIdx.x;
    const int warp  = tid >> 5;
    const int lane  = tid & 31;
    const int lbase = blockIdx.x * K2_LT;
    const int b     = blockIdx.y;

    const float* embs[NHEAD] = { e0, e1, e2, e3 };

    __shared__ float sm[K2_LT][K2_PAD];

    float4 acc[K2_WL][4];
#pragma unroll
    for (int il = 0; il < K2_WL; ++il)
#pragma unroll
        for (int c = 0; c < 4; ++c)
            acc[il][c] = make_float4(0.f, 0.f, 0.f, 0.f);

#pragma unroll
    for (int il = 0; il < K2_WL; ++il) {
        const int l = lbase + warp * K2_WL + il;
#pragma unroll
        for (int h = 0; h < NHEAD; ++h) {
            float4 tw = g_tw[((size_t)b * LCOLS + l) * NHEAD + h];
            unsigned pk = __float_as_uint(tw.w);
            float w[3]   = { tw.x, tw.y, tw.z };
            int   idx[3] = { (int)( pk        & 0x3FF),
                             (int)((pk >> 10) & 0x3FF),
                             (int)((pk >> 20) & 0x3FF) };
#pragma unroll
            for (int k = 0; k < 3; ++k) {
                const float4* row =
                    (const float4*)(embs[h] + (size_t)idx[k] * DDIM) + lane;
                const float wk = w[k];
#pragma unroll
                for (int c = 0; c < 4; ++c) {
                    float4 v = __ldg(row + c * 32);
                    acc[il][c].x = fmaf(wk, v.x, acc[il][c].x);
                    acc[il][c].y = fmaf(wk, v.y, acc[il][c].y);
                    acc[il][c].z = fmaf(wk, v.z, acc[il][c].z);
                    acc[il][c].w = fmaf(wk, v.w, acc[il][c].w);
                }
            }
        }
    }

    // accum (lanes over d) -> smem[l][d]
#pragma unroll
    for (int il = 0; il < K2_WL; ++il) {
        const int lrow = warp * K2_WL + il;
#pragma unroll
        for (int c = 0; c < 4; ++c)
            *(float4*)&sm[lrow][c * 128 + lane * 4] = acc[il][c];
    }
    __syncthreads();

    // coalesced stores: consecutive threads -> consecutive l
    float* obase = out + (size_t)b * DDIM * LCOLS + lbase;
#pragma unroll
    for (int r = 0; r < (DDIM * K2_LT) / 256; ++r) {
        int linear = r * 256 + tid;
        int d = linear >> 4;          // /16
        int l = linear & 15;
        obase[(size_t)d * LCOLS + l] = sm[l][d];
    }
}

// ---------------------------------------------------------------------------
extern "C" void kernel_launch(void* const* d_in, const int* in_sizes, int n_in,
                              void* d_out, int out_size)
{
    const float* logits = (const float*)d_in[0];
    const float* e0     = (const float*)d_in[1];
    const float* e1     = (const float*)d_in[2];
    const float* e2     = (const float*)d_in[3];
    const float* e3     = (const float*)d_in[4];
    float*       out    = (float*)d_out;

    dim3 g1(LCOLS / 128, NHEAD, BDIM);     // (16, 4, 8) = 512 blocks of 512 thr
    dim3 b1(128, 4, 1);
    topk_softmax_kernel<<<g1, b1>>>(logits);

    dim3 g2(LCOLS / K2_LT, BDIM, 1);       // (128, 8) = 1024 blocks of 256 thr
    combine_kernel<<<g2, 256>>>(e0, e1, e2, e3, out);
}